// round 1
// baseline (speedup 1.0000x reference)
#include <cuda_runtime.h>
#include <math.h>

// Problem constants
#define BB   2
#define SS   2048
#define DD   2048
#define HH   16
#define KVH  8
#define GG   2        // H / KV
#define HD   128
#define SCALE 0.08838834764831845f  // 1/sqrt(128)

// Scratch (zero-init .bss style device globals; no allocation)
__device__ float g_q[(size_t)BB * SS * HH  * HD];   // (B,S,H,HD)
__device__ float g_k[(size_t)BB * SS * KVH * HD];   // (B,S,KV,HD)
__device__ float g_v[(size_t)BB * SS * KVH * HD];   // (B,S,KV,HD)
__device__ float g_o[(size_t)BB * SS * HH  * HD];   // (B,S,H,HD)

// ---------------------------------------------------------------------------
// Generic SGEMM  C[M,N] = A[M,K] * B[N,K]^T   (both row-major, NT form)
// BM=BN=128, BK=8, 256 threads, 8x8 per-thread microtile.
// All dims are multiples of 128/8 in this problem -> no bounds checks.
// ---------------------------------------------------------------------------
__global__ __launch_bounds__(256) void sgemm_nt(
    int M, int N, int K,
    const float* __restrict__ A, int lda,
    const float* __restrict__ B, int ldb,
    float* __restrict__ C, int ldc)
{
    __shared__ float As[8][128];
    __shared__ float Bs[8][128];

    const int tx   = threadIdx.x;
    const int row0 = blockIdx.y * 128;
    const int col0 = blockIdx.x * 128;
    const int tr   = (tx >> 4) << 3;     // 0..120
    const int tc   = (tx & 15) << 3;     // 0..120
    const int lr   = tx >> 1;            // 0..127
    const int lc   = (tx & 1) << 2;      // 0 or 4

    float acc[8][8];
#pragma unroll
    for (int i = 0; i < 8; ++i)
#pragma unroll
        for (int j = 0; j < 8; ++j) acc[i][j] = 0.f;

    for (int k0 = 0; k0 < K; k0 += 8) {
        float4 a4 = *(const float4*)(A + (size_t)(row0 + lr) * lda + k0 + lc);
        float4 b4 = *(const float4*)(B + (size_t)(col0 + lr) * ldb + k0 + lc);
        As[lc + 0][lr] = a4.x; As[lc + 1][lr] = a4.y;
        As[lc + 2][lr] = a4.z; As[lc + 3][lr] = a4.w;
        Bs[lc + 0][lr] = b4.x; Bs[lc + 1][lr] = b4.y;
        Bs[lc + 2][lr] = b4.z; Bs[lc + 3][lr] = b4.w;
        __syncthreads();
#pragma unroll
        for (int k = 0; k < 8; ++k) {
            float4 a0 = *(const float4*)&As[k][tr];
            float4 a1 = *(const float4*)&As[k][tr + 4];
            float4 b0 = *(const float4*)&Bs[k][tc];
            float4 b1 = *(const float4*)&Bs[k][tc + 4];
            float ar[8] = {a0.x, a0.y, a0.z, a0.w, a1.x, a1.y, a1.z, a1.w};
            float br[8] = {b0.x, b0.y, b0.z, b0.w, b1.x, b1.y, b1.z, b1.w};
#pragma unroll
            for (int i = 0; i < 8; ++i)
#pragma unroll
                for (int j = 0; j < 8; ++j) acc[i][j] += ar[i] * br[j];
        }
        __syncthreads();
    }

#pragma unroll
    for (int i = 0; i < 8; ++i) {
        float4 v0 = make_float4(acc[i][0], acc[i][1], acc[i][2], acc[i][3]);
        float4 v1 = make_float4(acc[i][4], acc[i][5], acc[i][6], acc[i][7]);
        float* cp = C + (size_t)(row0 + tr + i) * ldc + col0 + tc;
        *(float4*)cp       = v0;
        *(float4*)(cp + 4) = v1;
    }
}

// ---------------------------------------------------------------------------
// Fused RMSNorm + RoPE, in place on (B,S,nheads,HD) layout.
// One block per (b,s,h), 128 threads (one per hd).
// ---------------------------------------------------------------------------
__global__ __launch_bounds__(128) void normrope_kernel(
    float* __restrict__ data, const float* __restrict__ w,
    const float* __restrict__ cosb, const float* __restrict__ sinb,
    int nheads)
{
    const int idx = blockIdx.x;
    const int h = idx % nheads;
    const int s = (idx / nheads) % SS;
    const int b = idx / (nheads * SS);
    const int t = threadIdx.x;

    float* ptr = data + (((size_t)b * SS + s) * nheads + h) * HD;
    float v = ptr[t];

    float ss = v * v;
#pragma unroll
    for (int o = 16; o; o >>= 1) ss += __shfl_xor_sync(0xffffffffu, ss, o);

    __shared__ float ws[4];
    __shared__ float sh[128];
    const int lane = t & 31, wid = t >> 5;
    if (lane == 0) ws[wid] = ss;
    __syncthreads();
    float var = (ws[0] + ws[1] + ws[2] + ws[3]) * (1.0f / HD);
    float xn = v * rsqrtf(var + 1e-6f) * w[t];
    sh[t] = xn;
    __syncthreads();
    float rot = (t < 64) ? -sh[t + 64] : sh[t - 64];

    const float* cp = cosb + ((size_t)b * SS + s) * HD;
    const float* sp = sinb + ((size_t)b * SS + s) * HD;
    ptr[t] = xn * cp[t] + rot * sp[t];
}

// ---------------------------------------------------------------------------
// Scores: attn_raw[bh, q, t] = SCALE * dot(Q[b,h,q,:], K[b,kv,t,:])
// Skips tiles entirely above the causal diagonal. No masking needed:
// softmax only reads t <= q and writes zeros above the diagonal.
// ---------------------------------------------------------------------------
__global__ __launch_bounds__(256) void score_kernel(
    const float* __restrict__ q, const float* __restrict__ k,
    float* __restrict__ attn)
{
    if (blockIdx.x > blockIdx.y) return;   // tile fully above diagonal
    const int bh = blockIdx.z;
    const int h = bh % HH, b = bh / HH, kv = h / GG;

    const float* A = q + ((size_t)b * SS * HH  + h ) * HD;  // lda = H*HD
    const float* B = k + ((size_t)b * SS * KVH + kv) * HD;  // ldb = KV*HD
    float*       C = attn + (size_t)bh * SS * SS;           // ldc = S
    const int lda = HH * HD, ldb = KVH * HD, ldc = SS;

    __shared__ float As[8][128];
    __shared__ float Bs[8][128];

    const int tx   = threadIdx.x;
    const int row0 = blockIdx.y * 128;
    const int col0 = blockIdx.x * 128;
    const int tr   = (tx >> 4) << 3;
    const int tc   = (tx & 15) << 3;
    const int lr   = tx >> 1;
    const int lc   = (tx & 1) << 2;

    float acc[8][8];
#pragma unroll
    for (int i = 0; i < 8; ++i)
#pragma unroll
        for (int j = 0; j < 8; ++j) acc[i][j] = 0.f;

    for (int k0 = 0; k0 < HD; k0 += 8) {
        float4 a4 = *(const float4*)(A + (size_t)(row0 + lr) * lda + k0 + lc);
        float4 b4 = *(const float4*)(B + (size_t)(col0 + lr) * ldb + k0 + lc);
        As[lc + 0][lr] = a4.x; As[lc + 1][lr] = a4.y;
        As[lc + 2][lr] = a4.z; As[lc + 3][lr] = a4.w;
        Bs[lc + 0][lr] = b4.x; Bs[lc + 1][lr] = b4.y;
        Bs[lc + 2][lr] = b4.z; Bs[lc + 3][lr] = b4.w;
        __syncthreads();
#pragma unroll
        for (int kk = 0; kk < 8; ++kk) {
            float4 a0 = *(const float4*)&As[kk][tr];
            float4 a1 = *(const float4*)&As[kk][tr + 4];
            float4 b0 = *(const float4*)&Bs[kk][tc];
            float4 b1 = *(const float4*)&Bs[kk][tc + 4];
            float ar[8] = {a0.x, a0.y, a0.z, a0.w, a1.x, a1.y, a1.z, a1.w};
            float br[8] = {b0.x, b0.y, b0.z, b0.w, b1.x, b1.y, b1.z, b1.w};
#pragma unroll
            for (int i = 0; i < 8; ++i)
#pragma unroll
                for (int j = 0; j < 8; ++j) acc[i][j] += ar[i] * br[j];
        }
        __syncthreads();
    }

#pragma unroll
    for (int i = 0; i < 8; ++i) {
        float4 v0 = make_float4(acc[i][0] * SCALE, acc[i][1] * SCALE,
                                acc[i][2] * SCALE, acc[i][3] * SCALE);
        float4 v1 = make_float4(acc[i][4] * SCALE, acc[i][5] * SCALE,
                                acc[i][6] * SCALE, acc[i][7] * SCALE);
        float* cp = C + (size_t)(row0 + tr + i) * ldc + col0 + tc;
        *(float4*)cp       = v0;
        *(float4*)(cp + 4) = v1;
    }
}

// ---------------------------------------------------------------------------
// Row softmax over attn[bh, q, :]; causal: only t <= q valid; zeros beyond.
// ---------------------------------------------------------------------------
__global__ __launch_bounds__(256) void softmax_kernel(float* __restrict__ attn)
{
    __shared__ float buf[SS];
    __shared__ float red[256];
    const int row = blockIdx.x;          // (b*H + h)*S + q
    const int qi = row % SS;
    const int valid = qi + 1;
    float* base = attn + (size_t)row * SS;
    const int tid = threadIdx.x;

    float m = -1e30f;
    for (int t = tid; t < valid; t += 256) {
        float v = base[t];
        buf[t] = v;
        m = fmaxf(m, v);
    }
    red[tid] = m; __syncthreads();
    for (int s2 = 128; s2; s2 >>= 1) {
        if (tid < s2) red[tid] = fmaxf(red[tid], red[tid + s2]);
        __syncthreads();
    }
    const float mx = red[0];
    __syncthreads();

    float sum = 0.f;
    for (int t = tid; t < valid; t += 256) {
        float e = expf(buf[t] - mx);
        buf[t] = e;
        sum += e;
    }
    red[tid] = sum; __syncthreads();
    for (int s2 = 128; s2; s2 >>= 1) {
        if (tid < s2) red[tid] += red[tid + s2];
        __syncthreads();
    }
    const float inv = 1.0f / red[0];

    for (int t = tid; t < SS; t += 256)
        base[t] = (t < valid) ? buf[t] * inv : 0.0f;
}

// ---------------------------------------------------------------------------
// AV: o[b,q,h,:] = sum_{t<=q} attn[bh,q,t] * V[b,kv,t,:]   (NN GEMM, causal K)
// N = HD = 128 -> single column tile.
// ---------------------------------------------------------------------------
__global__ __launch_bounds__(256) void av_kernel(
    const float* __restrict__ attn, const float* __restrict__ v,
    float* __restrict__ o)
{
    const int bh = blockIdx.z;
    const int h = bh % HH, b = bh / HH, kv = h / GG;

    const float* A  = attn + (size_t)bh * SS * SS;            // lda = S
    const float* Bv = v + ((size_t)b * SS * KVH + kv) * HD;   // ldb = KV*HD
    float*       C  = o + ((size_t)b * SS * HH  + h ) * HD;   // ldc = H*HD
    const int lda = SS, ldb = KVH * HD, ldc = HH * HD;

    __shared__ float As[8][128];
    __shared__ float Bs[8][128];

    const int tx   = threadIdx.x;
    const int row0 = blockIdx.y * 128;
    const int col0 = 0;
    const int tr   = (tx >> 4) << 3;
    const int tc   = (tx & 15) << 3;
    const int lr   = tx >> 1;            // A loader row
    const int lc   = (tx & 1) << 2;      // A loader col
    const int br_  = tx >> 5;            // B loader row (k within tile), 0..7
    const int bc_  = (tx & 31) << 2;     // B loader col, 0..124

    float acc[8][8];
#pragma unroll
    for (int i = 0; i < 8; ++i)
#pragma unroll
        for (int j = 0; j < 8; ++j) acc[i][j] = 0.f;

    const int Kmax = row0 + 128;   // causal: t <= q_max within this tile
    for (int k0 = 0; k0 < Kmax; k0 += 8) {
        float4 a4 = *(const float4*)(A + (size_t)(row0 + lr) * lda + k0 + lc);
        As[lc + 0][lr] = a4.x; As[lc + 1][lr] = a4.y;
        As[lc + 2][lr] = a4.z; As[lc + 3][lr] = a4.w;
        float4 b4 = *(const float4*)(Bv + (size_t)(k0 + br_) * ldb + col0 + bc_);
        *(float4*)&Bs[br_][bc_] = b4;
        __syncthreads();
#pragma unroll
        for (int kk = 0; kk < 8; ++kk) {
            float4 a0 = *(const float4*)&As[kk][tr];
            float4 a1 = *(const float4*)&As[kk][tr + 4];
            float4 b0 = *(const float4*)&Bs[kk][tc];
            float4 b1 = *(const float4*)&Bs[kk][tc + 4];
            float ar[8] = {a0.x, a0.y, a0.z, a0.w, a1.x, a1.y, a1.z, a1.w};
            float br[8] = {b0.x, b0.y, b0.z, b0.w, b1.x, b1.y, b1.z, b1.w};
#pragma unroll
            for (int i = 0; i < 8; ++i)
#pragma unroll
                for (int j = 0; j < 8; ++j) acc[i][j] += ar[i] * br[j];
        }
        __syncthreads();
    }

#pragma unroll
    for (int i = 0; i < 8; ++i) {
        float4 v0 = make_float4(acc[i][0], acc[i][1], acc[i][2], acc[i][3]);
        float4 v1 = make_float4(acc[i][4], acc[i][5], acc[i][6], acc[i][7]);
        float* cp = C + (size_t)(row0 + tr + i) * ldc + col0 + tc;
        *(float4*)cp       = v0;
        *(float4*)(cp + 4) = v1;
    }
}

// ---------------------------------------------------------------------------
// Launch
// ---------------------------------------------------------------------------
extern "C" void kernel_launch(void* const* d_in, const int* in_sizes, int n_in,
                              void* d_out, int out_size)
{
    const float* x    = (const float*)d_in[0];
    const float* cosb = (const float*)d_in[1];
    const float* sinb = (const float*)d_in[2];
    // d_in[3] = attention_mask (pure causal; applied analytically)
    const float* wq   = (const float*)d_in[4];
    const float* wk   = (const float*)d_in[5];
    const float* wv   = (const float*)d_in[6];
    const float* wo   = (const float*)d_in[7];
    const float* qw   = (const float*)d_in[8];
    const float* kw   = (const float*)d_in[9];

    float* out  = (float*)d_out;                              // (B,S,H*HD)
    float* attn = out + (size_t)BB * SS * HH * HD;            // (B,H,S,S)

    float *pq, *pk, *pv, *po;
    cudaGetSymbolAddress((void**)&pq, g_q);
    cudaGetSymbolAddress((void**)&pk, g_k);
    cudaGetSymbolAddress((void**)&pv, g_v);
    cudaGetSymbolAddress((void**)&po, g_o);

    const int BS = BB * SS;   // 4096
    dim3 blk(256);

    // QKV projections: C = X @ W^T
    sgemm_nt<<<dim3((HH * HD) / 128, BS / 128), blk>>>(
        BS, HH * HD, DD, x, DD, wq, DD, pq, HH * HD);
    sgemm_nt<<<dim3((KVH * HD) / 128, BS / 128), blk>>>(
        BS, KVH * HD, DD, x, DD, wk, DD, pk, KVH * HD);
    sgemm_nt<<<dim3((KVH * HD) / 128, BS / 128), blk>>>(
        BS, KVH * HD, DD, x, DD, wv, DD, pv, KVH * HD);

    // RMSNorm + RoPE (in place)
    normrope_kernel<<<BB * SS * HH, 128>>>(pq, qw, cosb, sinb, HH);
    normrope_kernel<<<BB * SS * KVH, 128>>>(pk, kw, cosb, sinb, KVH);

    // Scores (causal tiles only), softmax, AV
    score_kernel<<<dim3(SS / 128, SS / 128, BB * HH), blk>>>(pq, pk, attn);
    softmax_kernel<<<BB * HH * SS, 256>>>(attn);
    av_kernel<<<dim3(1, SS / 128, BB * HH), blk>>>(attn, pv, po);

    // Output projection: out = O @ Wo^T
    sgemm_nt<<<dim3(DD / 128, BS / 128), blk>>>(
        BS, DD, HH * HD, po, HH * HD, wo, HH * HD, out, DD);
}

// round 2
// speedup vs baseline: 2.6175x; 2.6175x over previous
#include <cuda_runtime.h>
#include <cuda_bf16.h>
#include <math.h>
#include <stdint.h>

// Problem constants
#define BB   2
#define SS   2048
#define DD   2048
#define HH   16
#define KVH  8
#define GG   2        // H / KV
#define HD   128
#define SCALE 0.08838834764831845f  // 1/sqrt(128)

// Scratch (device globals; no allocation)
__device__ float g_q[(size_t)BB * SS * HH  * HD];   // (B,S,H,HD)
__device__ float g_k[(size_t)BB * SS * KVH * HD];   // (B,S,KV,HD)
__device__ float g_v[(size_t)BB * SS * KVH * HD];   // (B,S,KV,HD)
__device__ float g_o[(size_t)BB * SS * HH  * HD];   // (B,S,H,HD)

// ---------------------------------------------------------------------------
// PTX helpers
// ---------------------------------------------------------------------------
__device__ __forceinline__ uint32_t smaddr(const void* p) {
    return (uint32_t)__cvta_generic_to_shared(p);
}

__device__ __forceinline__ void ldsm_x4(uint32_t* r, uint32_t addr) {
    asm volatile("ldmatrix.sync.aligned.m8n8.x4.shared.b16 {%0,%1,%2,%3}, [%4];"
        : "=r"(r[0]), "=r"(r[1]), "=r"(r[2]), "=r"(r[3]) : "r"(addr));
}
__device__ __forceinline__ void ldsm_x2(uint32_t* r, uint32_t addr) {
    asm volatile("ldmatrix.sync.aligned.m8n8.x2.shared.b16 {%0,%1}, [%2];"
        : "=r"(r[0]), "=r"(r[1]) : "r"(addr));
}
__device__ __forceinline__ void ldsm_x2t(uint32_t* r, uint32_t addr) {
    asm volatile("ldmatrix.sync.aligned.m8n8.x2.trans.shared.b16 {%0,%1}, [%2];"
        : "=r"(r[0]), "=r"(r[1]) : "r"(addr));
}
__device__ __forceinline__ void mma_bf16(float* c, const uint32_t* a, const uint32_t* b) {
    asm volatile(
        "mma.sync.aligned.m16n8k16.row.col.f32.bf16.bf16.f32 "
        "{%0,%1,%2,%3}, {%4,%5,%6,%7}, {%8,%9}, {%0,%1,%2,%3};"
        : "+f"(c[0]), "+f"(c[1]), "+f"(c[2]), "+f"(c[3])
        : "r"(a[0]), "r"(a[1]), "r"(a[2]), "r"(a[3]), "r"(b[0]), "r"(b[1]));
}

// ---------------------------------------------------------------------------
// bf16x3 split GEMM core.  C[128,128] tile of A[M,K] (row-major) times:
//   BTRANS=true : B[N,K] row-major (NT) ->  C = A * B^T
//   BTRANS=false: B[K,N] row-major (NN) ->  C = A * B
// Caller pre-offsets A, B, C to the tile origin. 256 threads.
// Each fp32 operand is split hi+lo (bf16); product = hi*hi + hi*lo + lo*hi.
// ---------------------------------------------------------------------------
#define AROW 40      // padded row length (bf16 elems) for [x][32] tiles
#define BROWN 136    // padded row length for NN B [32][128] tile

template<bool BTRANS>
__device__ __forceinline__ void gemm_core(
    const float* __restrict__ A, int lda,
    const float* __restrict__ B, int ldb,
    float* __restrict__ C, int ldc, int K, float alpha)
{
    __shared__ __align__(16) __nv_bfloat16 sAh[128 * AROW];
    __shared__ __align__(16) __nv_bfloat16 sAl[128 * AROW];
    __shared__ __align__(16) __nv_bfloat16 sBh[5120];
    __shared__ __align__(16) __nv_bfloat16 sBl[5120];

    const int tid  = threadIdx.x;
    const int lane = tid & 31;
    const int wid  = tid >> 5;
    const int wm   = (wid >> 2) << 6;   // 0 or 64
    const int wn   = (wid & 3) << 5;    // 0,32,64,96

    float acc[4][4][4];
#pragma unroll
    for (int i = 0; i < 4; ++i)
#pragma unroll
        for (int j = 0; j < 4; ++j)
#pragma unroll
            for (int l = 0; l < 4; ++l) acc[i][j][l] = 0.f;

    for (int k0 = 0; k0 < K; k0 += 32) {
        // ---- stage A tile (128 x 32) with hi/lo split ----
        {
            int r = tid >> 3;
            const int c = (tid & 7) << 2;
#pragma unroll
            for (int p = 0; p < 4; ++p, r += 32) {
                float4 v = *(const float4*)(A + (size_t)r * lda + k0 + c);
                __nv_bfloat162 H0 = __floats2bfloat162_rn(v.x, v.y);
                __nv_bfloat162 H1 = __floats2bfloat162_rn(v.z, v.w);
                __nv_bfloat162 L0 = __floats2bfloat162_rn(v.x - __low2float(H0),
                                                          v.y - __high2float(H0));
                __nv_bfloat162 L1 = __floats2bfloat162_rn(v.z - __low2float(H1),
                                                          v.w - __high2float(H1));
                *(__nv_bfloat162*)&sAh[r * AROW + c]     = H0;
                *(__nv_bfloat162*)&sAh[r * AROW + c + 2] = H1;
                *(__nv_bfloat162*)&sAl[r * AROW + c]     = L0;
                *(__nv_bfloat162*)&sAl[r * AROW + c + 2] = L1;
            }
        }
        // ---- stage B tile with hi/lo split ----
        if (BTRANS) {
            int r = tid >> 3;
            const int c = (tid & 7) << 2;
#pragma unroll
            for (int p = 0; p < 4; ++p, r += 32) {
                float4 v = *(const float4*)(B + (size_t)r * ldb + k0 + c);
                __nv_bfloat162 H0 = __floats2bfloat162_rn(v.x, v.y);
                __nv_bfloat162 H1 = __floats2bfloat162_rn(v.z, v.w);
                __nv_bfloat162 L0 = __floats2bfloat162_rn(v.x - __low2float(H0),
                                                          v.y - __high2float(H0));
                __nv_bfloat162 L1 = __floats2bfloat162_rn(v.z - __low2float(H1),
                                                          v.w - __high2float(H1));
                *(__nv_bfloat162*)&sBh[r * AROW + c]     = H0;
                *(__nv_bfloat162*)&sBh[r * AROW + c + 2] = H1;
                *(__nv_bfloat162*)&sBl[r * AROW + c]     = L0;
                *(__nv_bfloat162*)&sBl[r * AROW + c + 2] = L1;
            }
        } else {
            int r = tid >> 5;
            const int c = (tid & 31) << 2;
#pragma unroll
            for (int p = 0; p < 4; ++p, r += 8) {
                float4 v = *(const float4*)(B + (size_t)(k0 + r) * ldb + c);
                __nv_bfloat162 H0 = __floats2bfloat162_rn(v.x, v.y);
                __nv_bfloat162 H1 = __floats2bfloat162_rn(v.z, v.w);
                __nv_bfloat162 L0 = __floats2bfloat162_rn(v.x - __low2float(H0),
                                                          v.y - __high2float(H0));
                __nv_bfloat162 L1 = __floats2bfloat162_rn(v.z - __low2float(H1),
                                                          v.w - __high2float(H1));
                *(__nv_bfloat162*)&sBh[r * BROWN + c]     = H0;
                *(__nv_bfloat162*)&sBh[r * BROWN + c + 2] = H1;
                *(__nv_bfloat162*)&sBl[r * BROWN + c]     = L0;
                *(__nv_bfloat162*)&sBl[r * BROWN + c + 2] = L1;
            }
        }
        __syncthreads();

#pragma unroll
        for (int ks = 0; ks < 2; ++ks) {
            uint32_t af[4][4];
            uint32_t bh[4][2];
            uint32_t bl[4][2];

            const int arow_off = (lane & 15);
            const int akb = ks * 32 + ((lane >> 4) << 4);

            // A hi fragments
#pragma unroll
            for (int mt = 0; mt < 4; ++mt)
                ldsm_x4(af[mt], smaddr(&sAh[(wm + mt * 16 + arow_off) * AROW]) + akb);

            // B hi fragments
#pragma unroll
            for (int nt = 0; nt < 4; ++nt) {
                if (BTRANS) {
                    uint32_t ad = smaddr(&sBh[(wn + nt * 8 + (lane & 7)) * AROW])
                                + ks * 32 + (((lane >> 3) & 1) << 4);
                    ldsm_x2(bh[nt], ad);
                } else {
                    uint32_t ad = smaddr(&sBh[(ks * 16 + (lane & 15)) * BROWN + wn + nt * 8]);
                    ldsm_x2t(bh[nt], ad);
                }
            }
            // hi * hi
#pragma unroll
            for (int mt = 0; mt < 4; ++mt)
#pragma unroll
                for (int nt = 0; nt < 4; ++nt)
                    mma_bf16(acc[mt][nt], af[mt], bh[nt]);

            // B lo fragments; hi * lo
#pragma unroll
            for (int nt = 0; nt < 4; ++nt) {
                if (BTRANS) {
                    uint32_t ad = smaddr(&sBl[(wn + nt * 8 + (lane & 7)) * AROW])
                                + ks * 32 + (((lane >> 3) & 1) << 4);
                    ldsm_x2(bl[nt], ad);
                } else {
                    uint32_t ad = smaddr(&sBl[(ks * 16 + (lane & 15)) * BROWN + wn + nt * 8]);
                    ldsm_x2t(bl[nt], ad);
                }
            }
#pragma unroll
            for (int mt = 0; mt < 4; ++mt)
#pragma unroll
                for (int nt = 0; nt < 4; ++nt)
                    mma_bf16(acc[mt][nt], af[mt], bl[nt]);

            // A lo fragments; lo * hi
#pragma unroll
            for (int mt = 0; mt < 4; ++mt)
                ldsm_x4(af[mt], smaddr(&sAl[(wm + mt * 16 + arow_off) * AROW]) + akb);
#pragma unroll
            for (int mt = 0; mt < 4; ++mt)
#pragma unroll
                for (int nt = 0; nt < 4; ++nt)
                    mma_bf16(acc[mt][nt], af[mt], bh[nt]);
        }
        __syncthreads();
    }

    // ---- epilogue ----
#pragma unroll
    for (int mt = 0; mt < 4; ++mt) {
#pragma unroll
        for (int nt = 0; nt < 4; ++nt) {
            int r = wm + mt * 16 + (lane >> 2);
            int c = wn + nt * 8 + ((lane & 3) << 1);
            float2 v0 = make_float2(alpha * acc[mt][nt][0], alpha * acc[mt][nt][1]);
            float2 v1 = make_float2(alpha * acc[mt][nt][2], alpha * acc[mt][nt][3]);
            *(float2*)&C[(size_t)r * ldc + c]       = v0;
            *(float2*)&C[(size_t)(r + 8) * ldc + c] = v1;
        }
    }
}

// ---------------------------------------------------------------------------
// GEMM wrappers
// ---------------------------------------------------------------------------
__global__ __launch_bounds__(256, 2) void proj_mma(
    int K, const float* __restrict__ A, int lda,
    const float* __restrict__ B, int ldb, float* __restrict__ C, int ldc)
{
    const float* Ab = A + (size_t)blockIdx.y * 128 * lda;
    const float* Bb = B + (size_t)blockIdx.x * 128 * ldb;
    float* Cb = C + (size_t)blockIdx.y * 128 * ldc + (size_t)blockIdx.x * 128;
    gemm_core<true>(Ab, lda, Bb, ldb, Cb, ldc, K, 1.0f);
}

__global__ __launch_bounds__(256, 2) void score_mma(
    const float* __restrict__ q, const float* __restrict__ k, float* __restrict__ attn)
{
    if (blockIdx.x > blockIdx.y) return;       // tile above causal diagonal
    const int bh = blockIdx.z;
    const int h = bh % HH, b = bh / HH, kv = h / GG;
    const float* A = q + ((size_t)b * SS * HH + h) * HD
                       + (size_t)blockIdx.y * 128 * (HH * HD);
    const float* B = k + ((size_t)b * SS * KVH + kv) * HD
                       + (size_t)blockIdx.x * 128 * (KVH * HD);
    float* C = attn + (size_t)bh * SS * SS
                    + (size_t)blockIdx.y * 128 * SS + (size_t)blockIdx.x * 128;
    gemm_core<true>(A, HH * HD, B, KVH * HD, C, SS, HD, SCALE);
}

__global__ __launch_bounds__(256, 2) void av_mma(
    const float* __restrict__ attn, const float* __restrict__ v, float* __restrict__ o)
{
    const int bh = blockIdx.z;
    const int h = bh % HH, b = bh / HH, kv = h / GG;
    const float* A = attn + (size_t)bh * SS * SS + (size_t)blockIdx.y * 128 * SS;
    const float* B = v + ((size_t)b * SS * KVH + kv) * HD;
    float* C = o + ((size_t)b * SS * HH + h) * HD
                 + (size_t)blockIdx.y * 128 * (HH * HD);
    const int K = (int)blockIdx.y * 128 + 128;   // causal: t <= q_max in tile
    gemm_core<false>(A, SS, B, KVH * HD, C, HH * HD, K, 1.0f);
}

// ---------------------------------------------------------------------------
// Fused RMSNorm + RoPE, in place on (B,S,nheads,HD) layout.
// ---------------------------------------------------------------------------
__global__ __launch_bounds__(128) void normrope_kernel(
    float* __restrict__ data, const float* __restrict__ w,
    const float* __restrict__ cosb, const float* __restrict__ sinb,
    int nheads)
{
    const int idx = blockIdx.x;
    const int h = idx % nheads;
    const int s = (idx / nheads) % SS;
    const int b = idx / (nheads * SS);
    const int t = threadIdx.x;

    float* ptr = data + (((size_t)b * SS + s) * nheads + h) * HD;
    float v = ptr[t];

    float ss = v * v;
#pragma unroll
    for (int o = 16; o; o >>= 1) ss += __shfl_xor_sync(0xffffffffu, ss, o);

    __shared__ float ws[4];
    __shared__ float sh[128];
    const int lane = t & 31, wid = t >> 5;
    if (lane == 0) ws[wid] = ss;
    __syncthreads();
    float var = (ws[0] + ws[1] + ws[2] + ws[3]) * (1.0f / HD);
    float xn = v * rsqrtf(var + 1e-6f) * w[t];
    sh[t] = xn;
    __syncthreads();
    float rot = (t < 64) ? -sh[t + 64] : sh[t - 64];

    const float* cp = cosb + ((size_t)b * SS + s) * HD;
    const float* sp = sinb + ((size_t)b * SS + s) * HD;
    ptr[t] = xn * cp[t] + rot * sp[t];
}

// ---------------------------------------------------------------------------
// Row softmax over attn[bh, q, :]; causal: only t <= q valid; zeros beyond.
// ---------------------------------------------------------------------------
__global__ __launch_bounds__(256) void softmax_kernel(float* __restrict__ attn)
{
    __shared__ float buf[SS];
    __shared__ float red[256];
    const int row = blockIdx.x;          // (b*H + h)*S + q
    const int qi = row % SS;
    const int valid = qi + 1;
    float* base = attn + (size_t)row * SS;
    const int tid = threadIdx.x;

    float m = -1e30f;
    for (int t = tid; t < valid; t += 256) {
        float v = base[t];
        buf[t] = v;
        m = fmaxf(m, v);
    }
    red[tid] = m; __syncthreads();
    for (int s2 = 128; s2; s2 >>= 1) {
        if (tid < s2) red[tid] = fmaxf(red[tid], red[tid + s2]);
        __syncthreads();
    }
    const float mx = red[0];
    __syncthreads();

    float sum = 0.f;
    for (int t = tid; t < valid; t += 256) {
        float e = expf(buf[t] - mx);
        buf[t] = e;
        sum += e;
    }
    red[tid] = sum; __syncthreads();
    for (int s2 = 128; s2; s2 >>= 1) {
        if (tid < s2) red[tid] += red[tid + s2];
        __syncthreads();
    }
    const float inv = 1.0f / red[0];

    for (int t = tid; t < SS; t += 256)
        base[t] = (t < valid) ? buf[t] * inv : 0.0f;
}

// ---------------------------------------------------------------------------
// Launch
// ---------------------------------------------------------------------------
extern "C" void kernel_launch(void* const* d_in, const int* in_sizes, int n_in,
                              void* d_out, int out_size)
{
    const float* x    = (const float*)d_in[0];
    const float* cosb = (const float*)d_in[1];
    const float* sinb = (const float*)d_in[2];
    // d_in[3] = attention_mask (pure causal; applied analytically)
    const float* wq   = (const float*)d_in[4];
    const float* wk   = (const float*)d_in[5];
    const float* wv   = (const float*)d_in[6];
    const float* wo   = (const float*)d_in[7];
    const float* qw   = (const float*)d_in[8];
    const float* kw   = (const float*)d_in[9];

    float* out  = (float*)d_out;                              // (B,S,H*HD)
    float* attn = out + (size_t)BB * SS * HH * HD;            // (B,H,S,S)

    float *pq, *pk, *pv, *po;
    cudaGetSymbolAddress((void**)&pq, g_q);
    cudaGetSymbolAddress((void**)&pk, g_k);
    cudaGetSymbolAddress((void**)&pv, g_v);
    cudaGetSymbolAddress((void**)&po, g_o);

    const int BS = BB * SS;   // 4096
    dim3 blk(256);

    // QKV projections: C = X @ W^T
    proj_mma<<<dim3((HH * HD) / 128, BS / 128), blk>>>(
        DD, x, DD, wq, DD, pq, HH * HD);
    proj_mma<<<dim3((KVH * HD) / 128, BS / 128), blk>>>(
        DD, x, DD, wk, DD, pk, KVH * HD);
    proj_mma<<<dim3((KVH * HD) / 128, BS / 128), blk>>>(
        DD, x, DD, wv, DD, pv, KVH * HD);

    // RMSNorm + RoPE (in place)
    normrope_kernel<<<BB * SS * HH, 128>>>(pq, qw, cosb, sinb, HH);
    normrope_kernel<<<BB * SS * KVH, 128>>>(pk, kw, cosb, sinb, KVH);

    // Scores (causal tiles only), softmax, AV
    score_mma<<<dim3(SS / 128, SS / 128, BB * HH), blk>>>(pq, pk, attn);
    softmax_kernel<<<BB * HH * SS, 256>>>(attn);
    av_mma<<<dim3(1, SS / 128, BB * HH), blk>>>(attn, pv, po);

    // Output projection: out = O @ Wo^T
    proj_mma<<<dim3(DD / 128, BS / 128), blk>>>(
        BS == 0 ? 0 : (HH * HD), po, HH * HD, wo, HH * HD, out, DD);
}